// round 2
// baseline (speedup 1.0000x reference)
#include <cuda_runtime.h>
#include <cuda_bf16.h>
#include <math.h>

#define BDIM 4096
#define DDIM 512
#define NBINS 10
#define BM 128
#define BN 128
#define BK 16

// Scratch (no allocations allowed in kernel_launch)
__device__ float g_xn[BDIM * DDIM];   // normalized x
__device__ int   g_tgt[BDIM];         // targets cast to int32
__device__ int   g_cnt[NBINS];        // per-bin counts
__device__ float g_sum[NBINS];        // per-bin sum of (label - cos)^2

// ---------------------------------------------------------------------------
// Kernel 0: decode targets (handles int32 OR int64 storage), zero histograms.
// One block, 1024 threads. If stored as int64 (values 0..99), every odd
// int32 word is zero; if int32, the odd words are targets themselves and
// (for 4096 random values in [0,100)) cannot all be zero.
// ---------------------------------------------------------------------------
__global__ void decode_targets_kernel(const int* __restrict__ tgt_words) {
    __shared__ int s_any_odd;
    int tid = threadIdx.x;
    if (tid == 0) s_any_odd = 0;
    __syncthreads();

    int local = 0;
    #pragma unroll
    for (int r = 0; r < 4; r++) {
        int i = tid + r * 1024;           // element index 0..4095
        local |= tgt_words[2 * i + 1];    // odd word under int64 hypothesis
    }
    if (local) atomicOr(&s_any_odd, 1);
    __syncthreads();

    bool is32 = (s_any_odd != 0);
    #pragma unroll
    for (int r = 0; r < 4; r++) {
        int i = tid + r * 1024;
        g_tgt[i] = is32 ? tgt_words[i] : tgt_words[2 * i];
    }
    if (tid < NBINS) { g_cnt[tid] = 0; g_sum[tid] = 0.0f; }
}

// ---------------------------------------------------------------------------
// Kernel 1: row-normalize x
// grid = BDIM blocks, 128 threads (each thread owns one float4 of the row)
// ---------------------------------------------------------------------------
__global__ void prep_kernel(const float* __restrict__ x) {
    int row = blockIdx.x;
    int tid = threadIdx.x;  // 0..127

    float4 v = ((const float4*)(x + (size_t)row * DDIM))[tid];
    float ss = v.x * v.x + v.y * v.y + v.z * v.z + v.w * v.w;

    // block reduce (4 warps)
    #pragma unroll
    for (int o = 16; o > 0; o >>= 1) ss += __shfl_down_sync(0xffffffffu, ss, o);
    __shared__ float warp_s[4];
    if ((tid & 31) == 0) warp_s[tid >> 5] = ss;
    __syncthreads();
    float tot = warp_s[0] + warp_s[1] + warp_s[2] + warp_s[3];

    float inv = 1.0f / fmaxf(sqrtf(tot), 1e-12f);
    float4 o4;
    o4.x = v.x * inv; o4.y = v.y * inv; o4.z = v.z * inv; o4.w = v.w * inv;
    ((float4*)(g_xn + (size_t)row * DDIM))[tid] = o4;
}

// ---------------------------------------------------------------------------
// Kernel 2: fused symmetric Gram-matrix + histogram
// 32x32 grid of 128x128 tiles; only bx >= by computed (off-diag weight 2).
// 256 threads, 8x8 outputs per thread.
// ---------------------------------------------------------------------------
__global__ __launch_bounds__(256, 2) void ghm_main_kernel() {
    int by = blockIdx.y, bx = blockIdx.x;
    if (bx < by) return;  // symmetry: skip lower triangle of tiles

    __shared__ float As[BK][BM + 4];
    __shared__ float Bs[BK][BN + 4];
    __shared__ int   s_cnt[NBINS];
    __shared__ float s_sum[NBINS];
    __shared__ int   s_tr[BM];
    __shared__ int   s_tc[BN];

    int tid = threadIdx.x;
    if (tid < NBINS) { s_cnt[tid] = 0; s_sum[tid] = 0.0f; }
    if (tid < BM) {
        s_tr[tid] = g_tgt[by * BM + tid];
        s_tc[tid] = g_tgt[bx * BN + tid];
    }

    const float* Arow = g_xn + (size_t)by * BM * DDIM;
    const float* Brow = g_xn + (size_t)bx * BN * DDIM;

    float acc[8][8];
    #pragma unroll
    for (int m = 0; m < 8; m++)
        #pragma unroll
        for (int n = 0; n < 8; n++) acc[m][n] = 0.0f;

    int ty = tid >> 4, tx = tid & 15;

    for (int kk = 0; kk < DDIM; kk += BK) {
        // Load 128x16 A and B tiles: 512 float4s each, 2 per thread per matrix
        #pragma unroll
        for (int r = 0; r < 2; r++) {
            int p  = tid + r * 256;
            int i  = p >> 2;
            int kq = p & 3;
            float4 a = *(const float4*)(Arow + (size_t)i * DDIM + kk + kq * 4);
            float4 b = *(const float4*)(Brow + (size_t)i * DDIM + kk + kq * 4);
            As[kq * 4 + 0][i] = a.x; As[kq * 4 + 1][i] = a.y;
            As[kq * 4 + 2][i] = a.z; As[kq * 4 + 3][i] = a.w;
            Bs[kq * 4 + 0][i] = b.x; Bs[kq * 4 + 1][i] = b.y;
            Bs[kq * 4 + 2][i] = b.z; Bs[kq * 4 + 3][i] = b.w;
        }
        __syncthreads();

        #pragma unroll
        for (int k = 0; k < BK; k++) {
            float4 a0 = *(const float4*)&As[k][ty * 8];
            float4 a1 = *(const float4*)&As[k][ty * 8 + 4];
            float4 b0 = *(const float4*)&Bs[k][tx * 8];
            float4 b1 = *(const float4*)&Bs[k][tx * 8 + 4];
            float ra[8] = {a0.x, a0.y, a0.z, a0.w, a1.x, a1.y, a1.z, a1.w};
            float rb[8] = {b0.x, b0.y, b0.z, b0.w, b1.x, b1.y, b1.z, b1.w};
            #pragma unroll
            for (int m = 0; m < 8; m++)
                #pragma unroll
                for (int n = 0; n < 8; n++)
                    acc[m][n] += ra[m] * rb[n];
        }
        __syncthreads();
    }

    // Histogram this tile. Off-diagonal tiles represent (i,j) AND (j,i).
    bool diag = (bx == by);
    int   cinc = diag ? 1 : 2;
    float winc = diag ? 1.0f : 2.0f;

    // fp32 bin edges exactly as reference: edges[i] = i/10, edges[10] = 1 + 1e-6
    const float EDGE_LAST = 1.0f + 1e-6f;

    #pragma unroll
    for (int m = 0; m < 8; m++) {
        int i = ty * 8 + m;
        int tri = s_tr[i];
        #pragma unroll
        for (int n = 0; n < 8; n++) {
            int j = tx * 8 + n;
            float c   = acc[m][n];
            float lab = (tri == s_tc[j]) ? 1.0f : 0.0f;
            float dv  = lab - c;
            float g   = fabsf(dv);
            if (g < EDGE_LAST) {
                int idx = (g >= 0.1f) + (g >= 0.2f) + (g >= 0.3f) + (g >= 0.4f) +
                          (g >= 0.5f) + (g >= 0.6f) + (g >= 0.7f) + (g >= 0.8f) +
                          (g >= 0.9f);
                atomicAdd(&s_cnt[idx], cinc);
                atomicAdd(&s_sum[idx], winc * dv * dv);
            }
        }
    }
    __syncthreads();

    if (tid < NBINS) {
        if (s_cnt[tid]) {
            atomicAdd(&g_cnt[tid], s_cnt[tid]);
            atomicAdd(&g_sum[tid], s_sum[tid]);
        }
    }
}

// ---------------------------------------------------------------------------
// Kernel 3: finalize — EMA update, per-bin weights, scalar loss
// ---------------------------------------------------------------------------
__global__ void finalize_kernel(const float* __restrict__ acc_sum,
                                float* __restrict__ out) {
    if (threadIdx.x == 0 && blockIdx.x == 0) {
        const float tot = (float)BDIM * (float)BDIM;
        float vn = 0.0f;
        float cts[NBINS];
        #pragma unroll
        for (int b = 0; b < NBINS; b++) {
            cts[b] = (float)g_cnt[b];
            vn += cts[b];
        }
        float loss = 0.0f;
        #pragma unroll
        for (int b = 0; b < NBINS; b++) {
            float accn = 0.5f * acc_sum[b] + 0.5f * cts[b];  // momentum = 0.5
            float w = tot / (accn + 1e-6f);
            loss += g_sum[b] * w;
        }
        if (vn > 0.0f) loss /= vn;
        loss /= tot;  // mean over B*B elements
        *out = loss;
    }
}

extern "C" void kernel_launch(void* const* d_in, const int* in_sizes, int n_in,
                              void* d_out, int out_size) {
    const float* x       = (const float*)d_in[0];
    const float* acc_sum = (const float*)d_in[1];
    const int*   tgt     = (const int*)d_in[2];   // int32 view; kernel 0 sniffs layout
    float*       out     = (float*)d_out;

    decode_targets_kernel<<<1, 1024>>>(tgt);
    prep_kernel<<<BDIM, 128>>>(x);
    dim3 grid(BDIM / BN, BDIM / BM);
    ghm_main_kernel<<<grid, 256>>>();
    finalize_kernel<<<1, 32>>>(acc_sum, out);
}

// round 5
// speedup vs baseline: 7.0979x; 7.0979x over previous
#include <cuda_runtime.h>
#include <cuda_bf16.h>
#include <math.h>
#include <stdint.h>

#define BDIM 4096
#define DDIM 512
#define NBINS 10
#define TILE 128
#define NT   32            // tiles per dimension
#define NTRI 528           // NT*(NT+1)/2 upper-triangular tiles
#define BK   64            // bf16 K-elements per SMEM block
#define NKB  (DDIM / BK)   // 8 K-blocks
#define SROW 72            // padded SMEM row stride in bf16 (144 B) -> conflict-free ldmatrix
#define TILE_SMEM (TILE * SROW * 2)        // 18432 B per tile
#define DYN_SMEM  (4 * TILE_SMEM)          // A_hi, A_lo, B_hi, B_lo = 73728 B

// ---------------------------------------------------------------------------
// device scratch (no allocations allowed)
// ---------------------------------------------------------------------------
__device__ __nv_bfloat16 g_hi[BDIM * DDIM];
__device__ __nv_bfloat16 g_lo[BDIM * DDIM];
__device__ int   g_tgt[BDIM];
__device__ float g_cntf[NBINS];
__device__ float g_sum[NBINS];

// ---------------------------------------------------------------------------
// helpers (base-ISA only: ldmatrix + mma.sync, both sm_80+ / compute_103-safe)
// ---------------------------------------------------------------------------
__device__ __forceinline__ uint32_t smem_to_u32(const void* p) {
    uint32_t a;
    asm("{ .reg .u64 t; cvta.to.shared.u64 t, %1; cvt.u32.u64 %0, t; }"
        : "=r"(a) : "l"(p));
    return a;
}
__device__ __forceinline__ void ldsm_x4(uint32_t* r, uint32_t addr) {
    asm volatile("ldmatrix.sync.aligned.m8n8.x4.shared.b16 {%0,%1,%2,%3}, [%4];"
                 : "=r"(r[0]), "=r"(r[1]), "=r"(r[2]), "=r"(r[3]) : "r"(addr));
}
__device__ __forceinline__ void ldsm_x2(uint32_t* r, uint32_t addr) {
    asm volatile("ldmatrix.sync.aligned.m8n8.x2.shared.b16 {%0,%1}, [%2];"
                 : "=r"(r[0]), "=r"(r[1]) : "r"(addr));
}
__device__ __forceinline__ void mma_bf16(float* d, const uint32_t* a, const uint32_t* b) {
    asm volatile("mma.sync.aligned.m16n8k16.row.col.f32.bf16.bf16.f32 "
                 "{%0,%1,%2,%3}, {%4,%5,%6,%7}, {%8,%9}, {%0,%1,%2,%3};"
                 : "+f"(d[0]), "+f"(d[1]), "+f"(d[2]), "+f"(d[3])
                 : "r"(a[0]), "r"(a[1]), "r"(a[2]), "r"(a[3]),
                   "r"(b[0]), "r"(b[1]));
}

// ---------------------------------------------------------------------------
// Kernel 0: decode targets (sniffs int32 vs int64 storage), zero histograms.
// If stored as int64 (values 0..99), every odd int32 word is zero; if int32,
// odd words are targets themselves and cannot all be zero for 4096 randoms.
// ---------------------------------------------------------------------------
__global__ void decode_targets_kernel(const int* __restrict__ tgt_words) {
    __shared__ int s_any_odd;
    int tid = threadIdx.x;
    if (tid == 0) s_any_odd = 0;
    __syncthreads();

    int local = 0;
    #pragma unroll
    for (int r = 0; r < 4; r++) {
        int i = tid + r * 1024;
        local |= tgt_words[2 * i + 1];    // odd word under int64 hypothesis
    }
    if (local) atomicOr(&s_any_odd, 1);
    __syncthreads();

    bool is32 = (s_any_odd != 0);
    #pragma unroll
    for (int r = 0; r < 4; r++) {
        int i = tid + r * 1024;
        g_tgt[i] = is32 ? tgt_words[i] : tgt_words[2 * i];
    }
    if (tid < NBINS) { g_cntf[tid] = 0.0f; g_sum[tid] = 0.0f; }
}

// ---------------------------------------------------------------------------
// Kernel 1: normalize rows + split into bf16 hi/lo  (x = hi + lo)
// ---------------------------------------------------------------------------
__global__ void prep_kernel(const float* __restrict__ x) {
    int row = blockIdx.x;
    int tid = threadIdx.x;  // 0..127, one float4 per thread

    float4 v = ((const float4*)(x + (size_t)row * DDIM))[tid];
    float ss = v.x * v.x + v.y * v.y + v.z * v.z + v.w * v.w;
    #pragma unroll
    for (int o = 16; o > 0; o >>= 1) ss += __shfl_down_sync(0xffffffffu, ss, o);
    __shared__ float ws[4];
    if ((tid & 31) == 0) ws[tid >> 5] = ss;
    __syncthreads();
    float tot = ws[0] + ws[1] + ws[2] + ws[3];
    float inv = 1.0f / fmaxf(sqrtf(tot), 1e-12f);

    float f[4] = {v.x * inv, v.y * inv, v.z * inv, v.w * inv};
    __nv_bfloat16 h[4], l[4];
    #pragma unroll
    for (int i = 0; i < 4; i++) {
        h[i] = __float2bfloat16(f[i]);
        l[i] = __float2bfloat16(f[i] - __bfloat162float(h[i]));
    }
    size_t base = (size_t)row * DDIM + tid * 4;
    *(__nv_bfloat162*)(g_hi + base)     = __nv_bfloat162(h[0], h[1]);
    *(__nv_bfloat162*)(g_hi + base + 2) = __nv_bfloat162(h[2], h[3]);
    *(__nv_bfloat162*)(g_lo + base)     = __nv_bfloat162(l[0], l[1]);
    *(__nv_bfloat162*)(g_lo + base + 2) = __nv_bfloat162(l[2], l[3]);
}

// ---------------------------------------------------------------------------
// Kernel 2: mma.sync split-bf16 Gram tile + fused register histogram
// 528 upper-triangular tiles; 256 threads = 8 warps (2 x 4), warp tile 64x32
// ---------------------------------------------------------------------------
__global__ __launch_bounds__(256) void ghm_mma_kernel() {
    // triangular decode: tile t -> (by, bx), bx >= by
    int t = blockIdx.x;
    int by = (int)floorf(32.5f - 0.5f * sqrtf(4225.0f - 8.0f * (float)t));
    if (by < 0) by = 0;
    if (by > NT - 1) by = NT - 1;
    int S = by * NT - (by * (by - 1)) / 2;
    while (S + (NT - by) <= t) { S += NT - by; by++; }
    while (S > t) { by--; S -= NT - by; }
    int bx = by + (t - S);

    extern __shared__ char dynsmem[];
    __shared__ int   s_tr[TILE], s_tc[TILE];
    __shared__ float s_cnt[NBINS], s_sum[NBINS];

    int tid = threadIdx.x, wid = tid >> 5, lid = tid & 31;
    int warp_m = wid & 1;        // 0..1 -> 64-row band
    int warp_n = wid >> 1;       // 0..3 -> 32-col band

    if (tid < NBINS) { s_cnt[tid] = 0.0f; s_sum[tid] = 0.0f; }
    if (tid < TILE) {
        s_tr[tid] = g_tgt[by * TILE + tid];
        s_tc[tid] = g_tgt[bx * TILE + tid];
    }

    uint32_t smem_base = smem_to_u32(dynsmem);
    // tile order: A_hi, A_lo, B_hi, B_lo
    const uint32_t tile_off[4] = {0u, (uint32_t)TILE_SMEM,
                                  (uint32_t)(2 * TILE_SMEM), (uint32_t)(3 * TILE_SMEM)};

    float acc[4][4][4];
    #pragma unroll
    for (int mf = 0; mf < 4; mf++)
        #pragma unroll
        for (int nf = 0; nf < 4; nf++)
            #pragma unroll
            for (int r = 0; r < 4; r++) acc[mf][nf][r] = 0.0f;

    const __nv_bfloat16* gsrc[4] = {g_hi, g_lo, g_hi, g_lo};
    const int rbase[4] = {by * TILE, by * TILE, bx * TILE, bx * TILE};

    // per-lane ldmatrix address components (bytes)
    uint32_t a_row_off = (uint32_t)((warp_m * 64 + (lid & 15)) * SROW * 2);
    uint32_t a_col_off = (uint32_t)((lid >> 4) * 16);           // + ks*32 later
    uint32_t b_row_off = (uint32_t)((warp_n * 32 + (lid & 7)) * SROW * 2);
    uint32_t b_col_off = (uint32_t)(((lid >> 3) & 1) * 16);     // + ks*32 later

    for (int kb = 0; kb < NKB; kb++) {
        __syncthreads();
        // gmem -> smem: 4 tiles of 128 rows x 64 bf16 (128 B/row), 4 chunks/thread/tile
        #pragma unroll
        for (int tt = 0; tt < 4; tt++) {
            const __nv_bfloat16* src = gsrc[tt];
            int rb = rbase[tt];
            char* dst = dynsmem + tile_off[tt];
            #pragma unroll
            for (int rr = 0; rr < 4; rr++) {
                int p = rr * 256 + tid;
                int r = p >> 3, c = p & 7;
                uint4 v = *(const uint4*)(src + (size_t)(rb + r) * DDIM + kb * BK + c * 8);
                *(uint4*)(dst + r * (SROW * 2) + c * 16) = v;
            }
        }
        __syncthreads();

        // 3 terms: hi*hi, hi*lo, lo*hi
        #pragma unroll
        for (int term = 0; term < 3; term++) {
            uint32_t aT = smem_base + ((term == 2) ? tile_off[1] : tile_off[0]);
            uint32_t bT = smem_base + ((term == 1) ? tile_off[3] : tile_off[2]);
            #pragma unroll
            for (int ks = 0; ks < 4; ks++) {
                uint32_t af[4][4], bf[4][2];
                uint32_t kcol = (uint32_t)(ks * 32);
                #pragma unroll
                for (int mf = 0; mf < 4; mf++)
                    ldsm_x4(af[mf], aT + a_row_off + (uint32_t)(mf * 16 * SROW * 2)
                                       + kcol + a_col_off);
                #pragma unroll
                for (int nf = 0; nf < 4; nf++)
                    ldsm_x2(bf[nf], bT + b_row_off + (uint32_t)(nf * 8 * SROW * 2)
                                       + kcol + b_col_off);
                #pragma unroll
                for (int mf = 0; mf < 4; mf++)
                    #pragma unroll
                    for (int nf = 0; nf < 4; nf++)
                        mma_bf16(acc[mf][nf], af[mf], bf[nf]);
            }
        }
    }
    __syncthreads();

    // ------------------- epilogue: bin accumulators -------------------
    const float EDGE_LAST = 1.0f + 1e-6f;
    bool  diag = (bx == by);
    float wf   = diag ? 1.0f : 2.0f;   // off-diag tiles count (i,j) and (j,i)

    float bsum[NBINS], bcnt[NBINS];
    #pragma unroll
    for (int b = 0; b < NBINS; b++) { bsum[b] = 0.0f; bcnt[b] = 0.0f; }

    #pragma unroll
    for (int mf = 0; mf < 4; mf++) {
        int r0 = warp_m * 64 + mf * 16 + (lid >> 2);
        int tr0 = s_tr[r0], tr8 = s_tr[r0 + 8];
        #pragma unroll
        for (int nf = 0; nf < 4; nf++) {
            int c0 = warp_n * 32 + nf * 8 + (lid & 3) * 2;
            int tc0 = s_tc[c0], tc1 = s_tc[c0 + 1];
            int rowt[4] = {tr0, tr0, tr8, tr8};
            int colt[4] = {tc0, tc1, tc0, tc1};
            #pragma unroll
            for (int e = 0; e < 4; e++) {
                float cosv = acc[mf][nf][e];
                float lab  = (rowt[e] == colt[e]) ? 1.0f : 0.0f;
                float dv   = lab - cosv;
                float g    = fabsf(dv);
                int idx = (g >= 0.1f) + (g >= 0.2f) + (g >= 0.3f) + (g >= 0.4f) +
                          (g >= 0.5f) + (g >= 0.6f) + (g >= 0.7f) + (g >= 0.8f) +
                          (g >= 0.9f);
                bool  valid = g < EDGE_LAST;
                float sadd  = valid ? wf * dv * dv : 0.0f;
                float cadd  = valid ? wf : 0.0f;
                #pragma unroll
                for (int b = 0; b < NBINS; b++) {
                    bool hit = (idx == b);
                    bsum[b] += hit ? sadd : 0.0f;
                    bcnt[b] += hit ? cadd : 0.0f;
                }
            }
        }
    }

    #pragma unroll
    for (int b = 0; b < NBINS; b++) {
        #pragma unroll
        for (int o = 16; o > 0; o >>= 1) {
            bsum[b] += __shfl_down_sync(0xffffffffu, bsum[b], o);
            bcnt[b] += __shfl_down_sync(0xffffffffu, bcnt[b], o);
        }
    }
    if (lid == 0) {
        #pragma unroll
        for (int b = 0; b < NBINS; b++) {
            atomicAdd(&s_sum[b], bsum[b]);
            atomicAdd(&s_cnt[b], bcnt[b]);
        }
    }
    __syncthreads();
    if (tid < NBINS) {
        atomicAdd(&g_sum[tid], s_sum[tid]);
        atomicAdd(&g_cntf[tid], s_cnt[tid]);
    }
}

// ---------------------------------------------------------------------------
// Kernel 3: finalize — EMA update, per-bin weights, scalar loss
// ---------------------------------------------------------------------------
__global__ void finalize_kernel(const float* __restrict__ acc_sum,
                                float* __restrict__ out) {
    if (threadIdx.x == 0 && blockIdx.x == 0) {
        const float tot = (float)BDIM * (float)BDIM;
        float vn = 0.0f;
        #pragma unroll
        for (int b = 0; b < NBINS; b++) vn += g_cntf[b];
        float loss = 0.0f;
        #pragma unroll
        for (int b = 0; b < NBINS; b++) {
            float accn = 0.5f * acc_sum[b] + 0.5f * g_cntf[b];  // momentum = 0.5
            float w = tot / (accn + 1e-6f);
            loss += g_sum[b] * w;
        }
        if (vn > 0.0f) loss /= vn;
        loss /= tot;
        *out = loss;
    }
}

extern "C" void kernel_launch(void* const* d_in, const int* in_sizes, int n_in,
                              void* d_out, int out_size) {
    const float* x       = (const float*)d_in[0];
    const float* acc_sum = (const float*)d_in[1];
    const int*   tgt     = (const int*)d_in[2];   // int32 view; kernel 0 sniffs layout
    float*       out     = (float*)d_out;

    cudaFuncSetAttribute(ghm_mma_kernel,
                         cudaFuncAttributeMaxDynamicSharedMemorySize, DYN_SMEM);

    decode_targets_kernel<<<1, 1024>>>(tgt);
    prep_kernel<<<BDIM, 128>>>(x);
    ghm_mma_kernel<<<NTRI, 256, DYN_SMEM>>>();
    finalize_kernel<<<1, 32>>>(acc_sum, out);
}

// round 6
// speedup vs baseline: 8.4021x; 1.1837x over previous
#include <cuda_runtime.h>
#include <cuda_bf16.h>
#include <math.h>
#include <stdint.h>

#define BDIM 4096
#define DDIM 512
#define NBINS 10
#define TILE 128
#define NT   32            // tiles per dimension
#define NTRI 528           // NT*(NT+1)/2 upper-triangular tiles
#define KC   32            // bf16 K-elements per pipeline stage
#define NKB  (DDIM / KC)   // 16 stages
#define SROWB 80           // padded SMEM row stride in BYTES (64B data + 16B pad)
#define TILE_SMEMB (TILE * SROWB)     // 10240 B per tile
#define STAGE_B (4 * TILE_SMEMB)      // A_hi, A_lo, B_hi, B_lo = 40960 B
#define DYN_SMEM (2 * STAGE_B)        // double buffered = 81920 B

// ---------------------------------------------------------------------------
// device scratch (no allocations allowed)
// ---------------------------------------------------------------------------
__device__ __nv_bfloat16 g_hi[BDIM * DDIM];
__device__ __nv_bfloat16 g_lo[BDIM * DDIM];
__device__ int   g_tgt[BDIM];
__device__ float g_cntf[NBINS];
__device__ float g_sum[NBINS];
__device__ int   g_ticket;

// ---------------------------------------------------------------------------
// helpers (base-ISA only: cp.async, ldmatrix, mma.sync — all compute_103-safe)
// ---------------------------------------------------------------------------
__device__ __forceinline__ uint32_t smem_to_u32(const void* p) {
    uint32_t a;
    asm("{ .reg .u64 t; cvta.to.shared.u64 t, %1; cvt.u32.u64 %0, t; }"
        : "=r"(a) : "l"(p));
    return a;
}
__device__ __forceinline__ void cp16(uint32_t dst, const void* src) {
    asm volatile("cp.async.cg.shared.global [%0], [%1], 16;" :: "r"(dst), "l"(src));
}
#define CP_COMMIT() asm volatile("cp.async.commit_group;" ::: "memory")
#define CP_WAIT(n)  asm volatile("cp.async.wait_group %0;" :: "n"(n) : "memory")

__device__ __forceinline__ void ldsm_x4(uint32_t* r, uint32_t addr) {
    asm volatile("ldmatrix.sync.aligned.m8n8.x4.shared.b16 {%0,%1,%2,%3}, [%4];"
                 : "=r"(r[0]), "=r"(r[1]), "=r"(r[2]), "=r"(r[3]) : "r"(addr));
}
__device__ __forceinline__ void ldsm_x2(uint32_t* r, uint32_t addr) {
    asm volatile("ldmatrix.sync.aligned.m8n8.x2.shared.b16 {%0,%1}, [%2];"
                 : "=r"(r[0]), "=r"(r[1]) : "r"(addr));
}
__device__ __forceinline__ void mma_bf16(float* d, const uint32_t* a, const uint32_t* b) {
    asm volatile("mma.sync.aligned.m16n8k16.row.col.f32.bf16.bf16.f32 "
                 "{%0,%1,%2,%3}, {%4,%5,%6,%7}, {%8,%9}, {%0,%1,%2,%3};"
                 : "+f"(d[0]), "+f"(d[1]), "+f"(d[2]), "+f"(d[3])
                 : "r"(a[0]), "r"(a[1]), "r"(a[2]), "r"(a[3]),
                   "r"(b[0]), "r"(b[1]));
}

// ---------------------------------------------------------------------------
// Kernel 1: blocks 0..4095 normalize+split rows; block 4096 decodes targets
// (sniffs int32 vs int64 storage) and zeros the histogram/ticket state.
// ---------------------------------------------------------------------------
__global__ void prep_kernel(const float* __restrict__ x,
                            const int* __restrict__ tgt_words) {
    int blk = blockIdx.x;
    int tid = threadIdx.x;  // 0..127

    if (blk == BDIM) {
        // ---- target decode block ----
        __shared__ int s_any_odd;
        if (tid == 0) s_any_odd = 0;
        __syncthreads();
        int local = 0;
        #pragma unroll
        for (int r = 0; r < 32; r++) {
            int i = tid + r * 128;
            local |= tgt_words[2 * i + 1];   // odd word under int64 hypothesis
        }
        if (local) atomicOr(&s_any_odd, 1);
        __syncthreads();
        bool is32 = (s_any_odd != 0);
        #pragma unroll
        for (int r = 0; r < 32; r++) {
            int i = tid + r * 128;
            g_tgt[i] = is32 ? tgt_words[i] : tgt_words[2 * i];
        }
        if (tid < NBINS) { g_cntf[tid] = 0.0f; g_sum[tid] = 0.0f; }
        if (tid == 0) g_ticket = 0;
        return;
    }

    // ---- row normalize + bf16 hi/lo split ----
    float4 v = ((const float4*)(x + (size_t)blk * DDIM))[tid];
    float ss = v.x * v.x + v.y * v.y + v.z * v.z + v.w * v.w;
    #pragma unroll
    for (int o = 16; o > 0; o >>= 1) ss += __shfl_down_sync(0xffffffffu, ss, o);
    __shared__ float ws[4];
    if ((tid & 31) == 0) ws[tid >> 5] = ss;
    __syncthreads();
    float tot = ws[0] + ws[1] + ws[2] + ws[3];
    float inv = 1.0f / fmaxf(sqrtf(tot), 1e-12f);

    float f[4] = {v.x * inv, v.y * inv, v.z * inv, v.w * inv};
    __nv_bfloat16 h[4], l[4];
    #pragma unroll
    for (int i = 0; i < 4; i++) {
        h[i] = __float2bfloat16(f[i]);
        l[i] = __float2bfloat16(f[i] - __bfloat162float(h[i]));
    }
    size_t base = (size_t)blk * DDIM + tid * 4;
    *(__nv_bfloat162*)(g_hi + base)     = __nv_bfloat162(h[0], h[1]);
    *(__nv_bfloat162*)(g_hi + base + 2) = __nv_bfloat162(h[2], h[3]);
    *(__nv_bfloat162*)(g_lo + base)     = __nv_bfloat162(l[0], l[1]);
    *(__nv_bfloat162*)(g_lo + base + 2) = __nv_bfloat162(l[2], l[3]);
}

// ---------------------------------------------------------------------------
// stage loader: 4 tiles (A_hi, A_lo, B_hi, B_lo), 128 rows x 32 bf16 (64 B),
// rows padded to 80 B. 8 cp.async.128 per thread.
// ---------------------------------------------------------------------------
__device__ __forceinline__ void issue_stage(uint32_t sbase, int kb,
                                            int rowA, int rowB, int tid) {
    const __nv_bfloat16* gsrc[4] = {g_hi, g_lo, g_hi, g_lo};
    const int rb[4] = {rowA, rowA, rowB, rowB};
    #pragma unroll
    for (int tt = 0; tt < 4; tt++) {
        #pragma unroll
        for (int rr = 0; rr < 2; rr++) {
            int idx = rr * 256 + tid;
            int r = idx >> 2, c = idx & 3;
            const void* src = gsrc[tt] + (size_t)(rb[tt] + r) * DDIM + kb * KC + c * 8;
            cp16(sbase + tt * TILE_SMEMB + r * SROWB + c * 16, src);
        }
    }
}

// ---------------------------------------------------------------------------
// Kernel 2: pipelined mma.sync split-bf16 Gram tile + fused histogram +
// inline finalize by the last CTA (completion ticket).
// ---------------------------------------------------------------------------
__global__ __launch_bounds__(256, 2) void ghm_mma_kernel(
        const float* __restrict__ acc_sum, float* __restrict__ out) {
    // triangular decode: tile t -> (by, bx), bx >= by
    int t = blockIdx.x;
    int by = (int)floorf(32.5f - 0.5f * sqrtf(4225.0f - 8.0f * (float)t));
    if (by < 0) by = 0;
    if (by > NT - 1) by = NT - 1;
    int S = by * NT - (by * (by - 1)) / 2;
    while (S + (NT - by) <= t) { S += NT - by; by++; }
    while (S > t) { by--; S -= NT - by; }
    int bx = by + (t - S);
    int rowA = by * TILE, rowB = bx * TILE;

    extern __shared__ __align__(16) char dynsmem[];
    __shared__ int   s_tr[TILE], s_tc[TILE];
    __shared__ float s_cnt[NBINS], s_sum[NBINS];
    __shared__ int   s_last;

    int tid = threadIdx.x, wid = tid >> 5, lid = tid & 31;
    int warp_m = wid & 1;        // 0..1 -> 64-row band
    int warp_n = wid >> 1;       // 0..3 -> 32-col band

    if (tid < NBINS) { s_cnt[tid] = 0.0f; s_sum[tid] = 0.0f; }
    if (tid < TILE) {
        s_tr[tid] = g_tgt[rowA + tid];
        s_tc[tid] = g_tgt[rowB + tid];
    }

    uint32_t sb0 = smem_to_u32(dynsmem);
    uint32_t sb1 = sb0 + STAGE_B;

    float acc[4][4][4];
    #pragma unroll
    for (int mf = 0; mf < 4; mf++)
        #pragma unroll
        for (int nf = 0; nf < 4; nf++)
            #pragma unroll
            for (int r = 0; r < 4; r++) acc[mf][nf][r] = 0.0f;

    // per-lane ldmatrix address components (bytes)
    uint32_t a_off = (uint32_t)((warp_m * 64 + (lid & 15)) * SROWB + (lid >> 4) * 16);
    uint32_t b_off = (uint32_t)((warp_n * 32 + (lid & 7)) * SROWB + ((lid >> 3) & 1) * 16);

    issue_stage(sb0, 0, rowA, rowB, tid);
    CP_COMMIT();

    for (int kb = 0; kb < NKB; kb++) {
        uint32_t cur = (kb & 1) ? sb1 : sb0;
        if (kb + 1 < NKB) {
            issue_stage((kb & 1) ? sb0 : sb1, kb + 1, rowA, rowB, tid);
            CP_COMMIT();
            CP_WAIT(1);
        } else {
            CP_WAIT(0);
        }
        __syncthreads();

        uint32_t aHi = cur, aLo = cur + TILE_SMEMB;
        uint32_t bHi = cur + 2 * TILE_SMEMB, bLo = cur + 3 * TILE_SMEMB;

        #pragma unroll
        for (int ks = 0; ks < 2; ks++) {
            uint32_t kcol = (uint32_t)(ks * 32);
            uint32_t bh[4][2], bl[4][2];
            #pragma unroll
            for (int nf = 0; nf < 4; nf++) {
                uint32_t bo = b_off + (uint32_t)(nf * 8 * SROWB) + kcol;
                ldsm_x2(bh[nf], bHi + bo);
                ldsm_x2(bl[nf], bLo + bo);
            }
            #pragma unroll
            for (int mf = 0; mf < 4; mf++) {
                uint32_t ao = a_off + (uint32_t)(mf * 16 * SROWB) + kcol;
                uint32_t ah[4], al[4];
                ldsm_x4(ah, aHi + ao);
                ldsm_x4(al, aLo + ao);
                #pragma unroll
                for (int nf = 0; nf < 4; nf++) {
                    mma_bf16(acc[mf][nf], ah, bh[nf]);  // hi*hi
                    mma_bf16(acc[mf][nf], ah, bl[nf]);  // hi*lo
                    mma_bf16(acc[mf][nf], al, bh[nf]);  // lo*hi
                }
            }
        }
        __syncthreads();
    }

    // ------------------- epilogue: bin accumulators -------------------
    const float E10 = 1.0f + 1e-6f;           // last edge (fp32, as reference)
    float wf = (bx == by) ? 1.0f : 2.0f;      // off-diag tiles: (i,j) and (j,i)

    float bsum[NBINS], bcnt[NBINS];
    #pragma unroll
    for (int b = 0; b < NBINS; b++) { bsum[b] = 0.0f; bcnt[b] = 0.0f; }

    #pragma unroll
    for (int mf = 0; mf < 4; mf++) {
        int r0 = warp_m * 64 + mf * 16 + (lid >> 2);
        int tr0 = s_tr[r0], tr8 = s_tr[r0 + 8];
        #pragma unroll
        for (int nf = 0; nf < 4; nf++) {
            int c0 = warp_n * 32 + nf * 8 + (lid & 3) * 2;
            int tc0 = s_tc[c0], tc1 = s_tc[c0 + 1];
            int rowt[4] = {tr0, tr0, tr8, tr8};
            int colt[4] = {tc0, tc1, tc0, tc1};
            #pragma unroll
            for (int e = 0; e < 4; e++) {
                float cosv = acc[mf][nf][e];
                float lab  = (rowt[e] == colt[e]) ? 1.0f : 0.0f;
                float dv   = lab - cosv;
                float g    = fabsf(dv);
                // idx in 0..9 for valid g; 10 (matches no bin) if g >= last edge
                int idx = (g >= 0.1f) + (g >= 0.2f) + (g >= 0.3f) + (g >= 0.4f) +
                          (g >= 0.5f) + (g >= 0.6f) + (g >= 0.7f) + (g >= 0.8f) +
                          (g >= 0.9f) + (g >= E10);
                float g2 = dv * dv;
                #pragma unroll
                for (int b = 0; b < NBINS; b++) {
                    bool hit = (idx == b);
                    bsum[b] += hit ? g2 : 0.0f;
                    bcnt[b] += hit ? 1.0f : 0.0f;
                }
            }
        }
    }

    #pragma unroll
    for (int b = 0; b < NBINS; b++) {
        #pragma unroll
        for (int o = 16; o > 0; o >>= 1) {
            bsum[b] += __shfl_down_sync(0xffffffffu, bsum[b], o);
            bcnt[b] += __shfl_down_sync(0xffffffffu, bcnt[b], o);
        }
    }
    if (lid == 0) {
        #pragma unroll
        for (int b = 0; b < NBINS; b++) {
            atomicAdd(&s_sum[b], wf * bsum[b]);
            atomicAdd(&s_cnt[b], wf * bcnt[b]);
        }
    }
    __syncthreads();
    if (tid < NBINS) {
        atomicAdd(&g_sum[tid], s_sum[tid]);
        atomicAdd(&g_cntf[tid], s_cnt[tid]);
    }

    // ----------------- completion ticket: last CTA finalizes -----------------
    __syncthreads();
    if (tid == 0) {
        __threadfence();
        int done = atomicAdd(&g_ticket, 1);
        s_last = (done == NTRI - 1) ? 1 : 0;
    }
    __syncthreads();
    if (s_last && tid == 0) {
        const float tot = (float)BDIM * (float)BDIM;
        float cts[NBINS], sums[NBINS], vn = 0.0f;
        #pragma unroll
        for (int b = 0; b < NBINS; b++) {
            cts[b]  = atomicAdd(&g_cntf[b], 0.0f);  // L2-coherent read
            sums[b] = atomicAdd(&g_sum[b], 0.0f);
            vn += cts[b];
        }
        float loss = 0.0f;
        #pragma unroll
        for (int b = 0; b < NBINS; b++) {
            float accn = 0.5f * acc_sum[b] + 0.5f * cts[b];  // momentum = 0.5
            float w = tot / (accn + 1e-6f);
            loss += sums[b] * w;
        }
        if (vn > 0.0f) loss /= vn;
        loss /= tot;
        *out = loss;
    }
}

extern "C" void kernel_launch(void* const* d_in, const int* in_sizes, int n_in,
                              void* d_out, int out_size) {
    const float* x       = (const float*)d_in[0];
    const float* acc_sum = (const float*)d_in[1];
    const int*   tgt     = (const int*)d_in[2];   // int32 view; prep sniffs layout
    float*       out     = (float*)d_out;

    cudaFuncSetAttribute(ghm_mma_kernel,
                         cudaFuncAttributeMaxDynamicSharedMemorySize, DYN_SMEM);

    prep_kernel<<<BDIM + 1, 128>>>(x, tgt);
    ghm_mma_kernel<<<NTRI, 256, DYN_SMEM>>>(acc_sum, out);
}